// round 12
// baseline (speedup 1.0000x reference)
#include <cuda_runtime.h>
#include <math.h>

#define BB 16
#define NN 2000
#define CC 81
#define NPAD 2048
#define MAXC 64
#define MAXI 100
#define MIN_CONF 0.7f
#define NMS_TH 0.3f
#define FULL 0xffffffffu
#define GRID 144

// P1 streaming geometry
#define ROIS_PER_BLK 256
#define P1_BLOCKS    125                  // 125*256 = 32000 ROIs exactly
#define CH_ROIS      64
#define CH_BYTES     (CH_ROIS * CC * 4)   // 20736, multiple of 16
#define NCHUNK       4

// smem layout offsets (bytes)
#define OFF_BUF0 0
#define OFF_BUF1 20736
#define OFF_RES  41472                    // 256 x ull
#define OFF_MBAR 43520                    // 2 x 8B
#define SMEM_RAW 43536

typedef unsigned long long ull;

// Scratch (static device globals — no runtime allocation).
// Zero-init invariants: g_cnt reset to 0 by P2 each run; g_keep only ever
// written at candidate indices; barrier counters self-reset every use.
__device__ float4         g_bx[BB * NPAD];
__device__ float          g_sc[BB * NPAD];
__device__ int            g_cl[BB * NPAD];
__device__ unsigned char  g_keep[BB * NPAD];
__device__ int            g_cnt[BB * 80];
__device__ unsigned short g_slot[BB * 80 * MAXC];
__device__ unsigned           g_bar[2];
__device__ volatile unsigned  g_gen[2];

__device__ __forceinline__ unsigned smem_u32(const void* p) {
    unsigned a;
    asm("{ .reg .u64 t; cvta.to.shared.u64 t, %1; cvt.u32.u64 %0, t; }"
        : "=r"(a) : "l"(p));
    return a;
}

__device__ __forceinline__ void mbar_init(unsigned mbar, unsigned count) {
    asm volatile("mbarrier.init.shared.b64 [%0], %1;" :: "r"(mbar), "r"(count) : "memory");
}
__device__ __forceinline__ void mbar_expect_tx(unsigned mbar, unsigned bytes) {
    asm volatile("mbarrier.arrive.expect_tx.shared.b64 _, [%0], %1;"
                 :: "r"(mbar), "r"(bytes) : "memory");
}
__device__ __forceinline__ void bulk_g2s(unsigned dst, const void* src,
                                         unsigned bytes, unsigned mbar) {
    asm volatile("cp.async.bulk.shared::cluster.global.mbarrier::complete_tx::bytes "
                 "[%0], [%1], %2, [%3];"
                 :: "r"(dst), "l"(src), "r"(bytes), "r"(mbar) : "memory");
}
__device__ __forceinline__ void mbar_wait(unsigned mbar, unsigned parity) {
    unsigned done;
    asm volatile(
        "{\n\t.reg .pred p;\n\t"
        "mbarrier.try_wait.parity.acquire.cta.shared::cta.b64 p, [%1], %2;\n\t"
        "selp.b32 %0, 1, 0, p;\n\t}"
        : "=r"(done) : "r"(mbar), "r"(parity) : "memory");
    if (!done) {
        asm volatile(
            "{\n\t.reg .pred P1;\n\t"
            "WAIT_LOOP_%=:\n\t"
            "mbarrier.try_wait.parity.acquire.cta.shared::cta.b64 P1, [%0], %1, 0x989680;\n\t"
            "@P1 bra.uni WAIT_DONE_%=;\n\t"
            "bra.uni WAIT_LOOP_%=;\n\t"
            "WAIT_DONE_%=:\n\t}"
            :: "r"(mbar), "r"(parity) : "memory");
    }
}

// Grid-wide barrier: sense-reversing via generation counter. Counter resets
// to 0 on every use; generation is monotone across graph replays.
__device__ __forceinline__ void grid_barrier(int slot) {
    __threadfence();
    __syncthreads();
    if (threadIdx.x == 0) {
        unsigned g = g_gen[slot];
        unsigned t = atomicAdd(&g_bar[slot], 1u);
        if (t == GRID - 1) {
            g_bar[slot] = 0;
            __threadfence();
            g_gen[slot] = g + 1;
        } else {
            while (g_gen[slot] == g) { }
        }
    }
    __syncthreads();
    __threadfence();
}

// ---------------------------------------------------------------------------
// Warp-register bitonic sorts, descending. Pads (key 0) sink to the end.
// ---------------------------------------------------------------------------
__device__ __forceinline__ void bsort32(ull& k0, int lane) {
#pragma unroll
    for (int kk = 2; kk <= 32; kk <<= 1) {
#pragma unroll
        for (int d = kk >> 1; d > 0; d >>= 1) {
            ull o = __shfl_xor_sync(FULL, k0, d);
            bool lower = ((lane & d) == 0);
            bool asc   = ((lane & kk) == 0);
            k0 = (asc == lower) ? (k0 > o ? k0 : o) : (k0 > o ? o : k0);
        }
    }
}

__device__ __forceinline__ void bsort64(ull& k0, ull& k1, int lane) {
#pragma unroll
    for (int kk = 2; kk <= 64; kk <<= 1) {
#pragma unroll
        for (int d = kk >> 1; d > 0; d >>= 1) {
            if (d == 32) {
                ull mx = k0 > k1 ? k0 : k1;
                ull mn = k0 > k1 ? k1 : k0;
                k0 = mx; k1 = mn;
            } else {
                ull o0 = __shfl_xor_sync(FULL, k0, d);
                ull o1 = __shfl_xor_sync(FULL, k1, d);
                bool lower = ((lane & d) == 0);
                bool asc0  = ((lane & kk) == 0);
                bool asc1  = (((lane + 32) & kk) == 0);
                k0 = (asc0 == lower) ? (k0 > o0 ? k0 : o0) : (k0 > o0 ? o0 : k0);
                k1 = (asc1 == lower) ? (k1 > o1 ? k1 : o1) : (k1 > o1 ? o1 : k1);
            }
        }
    }
}

// ---------------------------------------------------------------------------
// Single persistent kernel: classify (bulk-async staged) -> barrier -> NMS ->
// barrier -> select.
// ---------------------------------------------------------------------------
__global__ void __launch_bounds__(1024, 1)
k_all(const float* __restrict__ rois,
      const float* __restrict__ probs,
      const float* __restrict__ deltas,
      float* __restrict__ out) {
    __shared__ __align__(16) unsigned char sraw[SMEM_RAW];
    __shared__ int wsum[32];
    __shared__ int wsuf[32];
    __shared__ int s_ncand;
    __shared__ int s_bstar;

    int bid  = blockIdx.x;
    int t    = threadIdx.x;
    int w    = t >> 5;
    int lane = t & 31;

    // ================= Phase 1: classify via cp.async.bulk pipeline =========
    // Block owns 256 contiguous ROIs; probs streamed in 4 chunks of 64 ROIs
    // through a double-buffered smem pipeline (bulk-async tracks completion
    // via mbarrier -> not limited by the per-SM LDG outstanding ceiling).
    if (bid < P1_BLOCKS) {
        unsigned sbase = smem_u32(sraw);
        unsigned mb0   = sbase + OFF_MBAR;
        unsigned mb1   = sbase + OFF_MBAR + 8;
        ull* res       = (ull*)(sraw + OFF_RES);

        if (t == 0) { mbar_init(mb0, 1); mbar_init(mb1, 1); }
        __syncthreads();

        const char* src0 = (const char*)probs + (size_t)bid * (ROIS_PER_BLK * CC * 4);
        if (t == 0) {
            mbar_expect_tx(mb0, CH_BYTES);
            bulk_g2s(sbase + OFF_BUF0, src0, CH_BYTES, mb0);
        }

#pragma unroll
        for (int k = 0; k < NCHUNK; k++) {
            unsigned mbk  = (k & 1) ? mb1 : mb0;
            unsigned bufo = (k & 1) ? OFF_BUF1 : OFF_BUF0;
            if (t == 0 && k + 1 < NCHUNK) {
                unsigned mbn  = ((k + 1) & 1) ? mb1 : mb0;
                unsigned bufn = ((k + 1) & 1) ? OFF_BUF1 : OFF_BUF0;
                mbar_expect_tx(mbn, CH_BYTES);
                bulk_g2s(sbase + bufn, src0 + (size_t)(k + 1) * CH_BYTES, CH_BYTES, mbn);
            }
            mbar_wait(mbk, (unsigned)(k >> 1));   // mbar i used at k=i, i+2

            const float* buf = (const float*)(sraw + bufo);
#pragma unroll
            for (int j = 0; j < 2; j++) {
                int r = CH_ROIS * k + 2 * w + j;          // block-local ROI
                const float* pr = buf + (2 * w + j) * CC;
                // conflict-free LDS: lane, lane+32, lane+64(<81)
                float bv = pr[lane];
                int   bc = lane;
                float v1 = pr[lane + 32];
                if (v1 > bv) { bv = v1; bc = lane + 32; }
                if (lane < CC - 64) {
                    float v2 = pr[lane + 64];
                    if (v2 > bv) { bv = v2; bc = lane + 64; }
                }
                // butterfly max, tie -> lowest class (matches jnp.argmax)
#pragma unroll
                for (int off = 16; off; off >>= 1) {
                    float ov = __shfl_down_sync(FULL, bv, off);
                    int   oi = __shfl_down_sync(FULL, bc, off);
                    if (ov > bv || (ov == bv && oi < bc)) { bv = ov; bc = oi; }
                }
                if (lane == 0)
                    res[r] = ((ull)__float_as_uint(bv) << 32) | (unsigned)bc;
            }
            __syncthreads();   // buffer consumed; safe to refill at k+2
        }

        // Tails: warp w owns ROIs [8w, 8w+8); 8 lanes run gathers in parallel.
        if (lane < 8) {
            int   r  = 8 * w + lane;
            int   g  = bid * ROIS_PER_BLK + r;
            float4 myroi = __ldg((const float4*)rois + g);
            ull   key = res[r];
            int   bi  = (int)(key & 0xFFFFull);
            float sv  = __uint_as_float((unsigned)(key >> 32));

            float4 d = __ldg((const float4*)deltas + ((size_t)g * CC + bi));
            float h  = myroi.z - myroi.x;
            float ww = myroi.w - myroi.y;
            float cy = myroi.x + 0.5f * h;
            float cx = myroi.y + 0.5f * ww;
            cy += d.x * 0.1f * h;
            cx += d.y * 0.1f * ww;
            h  *= expf(d.z * 0.2f);
            ww *= expf(d.w * 0.2f);
            float y1 = fminf(fmaxf(cy - 0.5f * h,  0.f), 1.f);
            float x1 = fminf(fmaxf(cx - 0.5f * ww, 0.f), 1.f);
            float y2 = fminf(fmaxf(cy + 0.5f * h,  0.f), 1.f);
            float x2 = fminf(fmaxf(cx + 0.5f * ww, 0.f), 1.f);

            bool valid = (bi > 0) && (sv >= MIN_CONF);
            int  b = g / NN;
            int  n = g - b * NN;
            int  o = b * NPAD + n;
            g_bx[o] = make_float4(y1, x1, y2, x2);
            g_cl[o] = bi;
            g_sc[o] = valid ? sv : -1.0f;
            if (valid) {
                int cidx = b * 80 + (bi - 1);
                int pos  = atomicAdd(&g_cnt[cidx], 1);
                if (pos < MAXC) g_slot[cidx * MAXC + pos] = (unsigned short)n;
            }
        }
    }

    grid_barrier(0);

    // ================= Phase 2: per-class NMS, full-chip spread =============
    // task = w*GRID + bid -> warps 0..8 active in every block (1280 tasks).
    // Cross-class IoU is exactly 0 (class offset 2 on clipped [0,1] boxes),
    // so per-class greedy == reference global greedy NMS.
    {
        float4* sbox = (float4*)(sraw);                   // [9][64]
        float*  sar  = (float*) (sraw + 9216);            // [9][64]
        int gw = w * GRID + bid;
        if (gw < BB * 80) {
            int b  = gw / 80;
            int gb = b * NPAD;
            int cnt = min(g_cnt[gw], MAXC);

            ull k0 = 0, k1 = 0;
            if (lane < cnt) {
                int idx = g_slot[gw * MAXC + lane];
                k0 = ((ull)__float_as_uint(g_sc[gb + idx]) << 32) | (ull)(0xFFFFFFFFu - (unsigned)idx);
            }
            if (lane + 32 < cnt) {
                int idx = g_slot[gw * MAXC + lane + 32];
                k1 = ((ull)__float_as_uint(g_sc[gb + idx]) << 32) | (ull)(0xFFFFFFFFu - (unsigned)idx);
            }
            if (cnt <= 32) bsort32(k0, lane);
            else           bsort64(k0, k1, lane);

            bool v0 = (lane < cnt);
            bool v1 = (lane + 32 < cnt);
            int  i0 = (int)(0xFFFFFFFFu - (unsigned)k0);
            int  i1 = (int)(0xFFFFFFFFu - (unsigned)k1);
            float4 B0 = v0 ? g_bx[gb + i0] : make_float4(0.f, 0.f, 0.f, 0.f);
            float4 B1 = v1 ? g_bx[gb + i1] : make_float4(0.f, 0.f, 0.f, 0.f);
            float a0 = (B0.z - B0.x) * (B0.w - B0.y);
            float a1 = (B1.z - B1.x) * (B1.w - B1.y);
            sbox[w * MAXC + lane]      = B0;  sar[w * MAXC + lane]      = a0;
            sbox[w * MAXC + lane + 32] = B1;  sar[w * MAXC + lane + 32] = a1;
            __syncwarp();

            // forward masks: f bit j set iff j > e and IoU(e,j) > thresh
            ull f0 = 0, f1 = 0;
#pragma unroll 4
            for (int j = 0; j < cnt; j++) {
                float4 bj = sbox[w * MAXC + j];
                float  aj = sar [w * MAXC + j];
                if (v0 && j > lane) {
                    float ih = fmaxf(fminf(B0.z, bj.z) - fmaxf(B0.x, bj.x), 0.f);
                    float iw = fmaxf(fminf(B0.w, bj.w) - fmaxf(B0.y, bj.y), 0.f);
                    float inter = ih * iw;
                    if (inter > NMS_TH * fmaxf(a0 + aj - inter, 1e-8f)) f0 |= 1ull << j;
                }
                if (v1 && j > lane + 32) {
                    float ih = fmaxf(fminf(B1.z, bj.z) - fmaxf(B1.x, bj.x), 0.f);
                    float iw = fmaxf(fminf(B1.w, bj.w) - fmaxf(B1.y, bj.y), 0.f);
                    float inter = ih * iw;
                    if (inter > NMS_TH * fmaxf(a1 + aj - inter, 1e-8f)) f1 |= 1ull << j;
                }
            }

            // greedy: take best alive, keep it, kill whom it suppresses.
            ull alive = (cnt >= 64) ? ~0ull : ((1ull << cnt) - 1ull);
            ull kept  = 0;
            while (alive) {
                int i = __ffsll((long long)alive) - 1;
                kept |= 1ull << i;
                ull fi = __shfl_sync(FULL, (i >= 32) ? f1 : f0, i & 31);
                alive &= ~fi;
                alive &= ~(1ull << i);
            }

            if (v0) g_keep[gb + i0] = (unsigned char)((kept >> lane) & 1ull);
            if (v1) g_keep[gb + i1] = (unsigned char)((kept >> (lane + 32)) & 1ull);
            if (lane == 0) g_cnt[gw] = 0;   // restore zero-invariant
        }
    }

    grid_barrier(1);

    // ================= Phase 3: radix-select + rank-emit (blocks 0-15) ======
    if (bid >= BB) return;
    {
        int*  hist = (int*)sraw;                 // [2048]
        ull*  cand = (ull*)(sraw + 8192);        // [256]
        int   b    = bid;
        int   gb   = b * NPAD;
        float* ob  = out + b * (MAXI * 6);

        for (int i = t; i < 2048; i += 1024) hist[i] = 0;
        if (t == 0) { s_ncand = 0; s_bstar = 0; }
        for (int i = t; i < MAXI * 6; i += 1024) ob[i] = 0.0f;
        __syncthreads();

        // histogram on float bits; kept => score in (0.7,1) -> bucket [819,2047]
        for (int i = t; i < NN; i += 1024) {
            if (g_keep[gb + i]) {
                unsigned bits = __float_as_uint(g_sc[gb + i]);
                int bk = (int)((bits - 0x3F000000u) >> 12);
                bk = min(2047, max(0, bk));
                atomicAdd(&hist[bk], 1);
            }
        }
        __syncthreads();

        // two-level suffix scan: thread t covers buckets {2t, 2t+1};
        // find b* = max bucket with suffix count >= 100 (unique transition)
        {
            int h0  = hist[2 * t];
            int h1  = hist[2 * t + 1];
            int loc = h0 + h1;
            int suf = loc;
            for (int d = 1; d < 32; d <<= 1) {
                int v = __shfl_down_sync(FULL, suf, d);
                if (lane + d < 32) suf += v;
            }
            if (lane == 0) wsum[w] = suf;
            __syncthreads();
            if (t == 0) {
                int acc = 0;
                for (int w2 = 31; w2 >= 0; w2--) { wsuf[w2] = acc; acc += wsum[w2]; }
            }
            __syncthreads();
            int run = wsuf[w] + (suf - loc);
            int S = run + h1;
            if (S >= MAXI && run < MAXI) s_bstar = 2 * t + 1;
            run = S;
            S = run + h0;
            if (S >= MAXI && run < MAXI) s_bstar = 2 * t;
        }
        __syncthreads();

        unsigned tbits = 0x3F000000u + ((unsigned)s_bstar << 12);
        for (int i = t; i < NN; i += 1024) {
            if (g_keep[gb + i]) {
                unsigned bits = __float_as_uint(g_sc[gb + i]);
                if (bits >= tbits) {
                    int p = atomicAdd(&s_ncand, 1);
                    if (p < 256)
                        cand[p] = ((ull)bits << 32) | (ull)(0xFFFFFFFFu - (unsigned)i);
                }
            }
        }
        __syncthreads();

        // rank-based emit: thread t handles candidate t; rank = number of
        // strictly greater keys (keys distinct). No sort, no barriers.
        int m = min(s_ncand, 256);
        if (t < m) {
            ull my = cand[t];
            int rank = 0;
            for (int j = 0; j < m; j++) rank += (cand[j] > my);
            if (rank < MAXI) {
                int idx = (int)(0xFFFFFFFFu - (unsigned)my);
                float sc = __uint_as_float((unsigned)(my >> 32));
                float4 bx = g_bx[gb + idx];
                float* row = ob + rank * 6;
                row[0] = bx.x; row[1] = bx.y; row[2] = bx.z; row[3] = bx.w;
                row[4] = (float)g_cl[gb + idx]; row[5] = sc;
            }
        }
    }
}

// ---------------------------------------------------------------------------
extern "C" void kernel_launch(void* const* d_in, const int* in_sizes, int n_in,
                              void* d_out, int out_size) {
    const float* rois   = nullptr;
    const float* probs  = nullptr;
    const float* deltas = nullptr;
    for (int i = 0; i < n_in; i++) {
        if      (in_sizes[i] == BB * NN * 4)      rois   = (const float*)d_in[i];
        else if (in_sizes[i] == BB * NN * CC)     probs  = (const float*)d_in[i];
        else if (in_sizes[i] == BB * NN * CC * 4) deltas = (const float*)d_in[i];
    }
    float* out = (float*)d_out;

    k_all<<<GRID, 1024>>>(rois, probs, deltas, out);
}

// round 13
// speedup vs baseline: 1.5006x; 1.5006x over previous
#include <cuda_runtime.h>
#include <math.h>

#define BB 16
#define NN 2000
#define CC 81
#define NPAD 2048
#define MAXC 64
#define MAXI 100
#define MIN_CONF 0.7f
#define NMS_TH 0.3f
#define FULL 0xffffffffu
#define GRID 148

typedef unsigned long long ull;

// Scratch (static device globals — no runtime allocation).
// Zero-init invariants: g_cnt reset to 0 by P2 each run; g_ndone reset by P3
// blocks; g_keep only ever written at candidate indices; barrier counters
// self-reset every use.
__device__ float4         g_bx[BB * NPAD];
__device__ float          g_sc[BB * NPAD];
__device__ int            g_cl[BB * NPAD];
__device__ unsigned char  g_keep[BB * NPAD];
__device__ int            g_cnt[BB * 80];
__device__ unsigned short g_slot[BB * 80 * MAXC];
__device__ int            g_ndone[BB];      // NMS tasks done per batch (80)
__device__ unsigned           g_bar[1];
__device__ volatile unsigned  g_gen[1];

// Grid-wide barrier: sense-reversing via generation counter. Counter resets
// to 0 on every use; generation is monotone across graph replays.
__device__ __forceinline__ void grid_barrier(int slot) {
    __threadfence();
    __syncthreads();
    if (threadIdx.x == 0) {
        unsigned g = g_gen[slot];
        unsigned t = atomicAdd(&g_bar[slot], 1u);
        if (t == GRID - 1) {
            g_bar[slot] = 0;
            __threadfence();
            g_gen[slot] = g + 1;
        } else {
            while (g_gen[slot] == g) { }
        }
    }
    __syncthreads();
    __threadfence();
}

// ---------------------------------------------------------------------------
// Warp-register bitonic sorts, descending. Pads (key 0) sink to the end.
// ---------------------------------------------------------------------------
__device__ __forceinline__ void bsort32(ull& k0, int lane) {
#pragma unroll
    for (int kk = 2; kk <= 32; kk <<= 1) {
#pragma unroll
        for (int d = kk >> 1; d > 0; d >>= 1) {
            ull o = __shfl_xor_sync(FULL, k0, d);
            bool lower = ((lane & d) == 0);
            bool asc   = ((lane & kk) == 0);
            k0 = (asc == lower) ? (k0 > o ? k0 : o) : (k0 > o ? o : k0);
        }
    }
}

__device__ __forceinline__ void bsort64(ull& k0, ull& k1, int lane) {
#pragma unroll
    for (int kk = 2; kk <= 64; kk <<= 1) {
#pragma unroll
        for (int d = kk >> 1; d > 0; d >>= 1) {
            if (d == 32) {
                ull mx = k0 > k1 ? k0 : k1;
                ull mn = k0 > k1 ? k1 : k0;
                k0 = mx; k1 = mn;
            } else {
                ull o0 = __shfl_xor_sync(FULL, k0, d);
                ull o1 = __shfl_xor_sync(FULL, k1, d);
                bool lower = ((lane & d) == 0);
                bool asc0  = ((lane & kk) == 0);
                bool asc1  = (((lane + 32) & kk) == 0);
                k0 = (asc0 == lower) ? (k0 > o0 ? k0 : o0) : (k0 > o0 ? o0 : k0);
                k1 = (asc1 == lower) ? (k1 > o1 ? k1 : o1) : (k1 > o1 ? o1 : k1);
            }
        }
    }
}

// ---------------------------------------------------------------------------
// Single persistent kernel: classify -> barrier -> NMS -> (per-batch ready
// counters) -> select on blocks 0-15; blocks 16+ exit after NMS.
// ---------------------------------------------------------------------------
__global__ void __launch_bounds__(1024, 1)
k_all(const float* __restrict__ rois,
      const float* __restrict__ probs,
      const float* __restrict__ deltas,
      float* __restrict__ out) {
    // smem reuse (phases separated by barrier / block syncs):
    //  P1: slots[32][8] ull at [0, 2048)
    //  P2: sbox[9][64] float4 at [2048, 11264) + sar[9][64] at [11264, 13568)
    //  P3: hist[2048] int at [0, 8192) + cand[256] ull at [8192, 10240)
    __shared__ __align__(16) unsigned char sraw[13568];
    __shared__ int wsum[32];
    __shared__ int wsuf[32];
    __shared__ int s_ncand;
    __shared__ int s_bstar;

    int bid  = blockIdx.x;
    int t    = threadIdx.x;
    int w    = t >> 5;
    int lane = t & 31;

    // ================= Phase 1: classify (one warp per 8 ROIs) =============
    // Fixed-trip unrolled LDG.128 loop (lanes own 5-6 contiguous float4s of
    // the warp's 648-float probs region; iter 5 predicated). Per-ROI packed
    // argmax keys combine via 8 per-warp shared u64 atomicMax slots; 8 lanes
    // run refine tails concurrently. No block-wide sync in this phase.
    {
        ull* slots = (ull*)sraw + w * 8;
        if (lane < 8) slots[lane] = 0;
        __syncwarp();

        int task = w * GRID + bid;
        if (task < (BB * NN) / 8) {
            float4 myroi = make_float4(0.f, 0.f, 0.f, 0.f);
            if (lane < 8) myroi = __ldg((const float4*)rois + (task * 8 + lane));

            const float4* pq = (const float4*)(probs + (size_t)task * 648);
            int q0 = (162 * lane) >> 5;
            int q1 = (162 * (lane + 1)) >> 5;    // q1-q0 in {5,6}
            int p   = q0 * 4;
            int roi = p / 81;
            int c   = p - roi * 81;
            ull keyA = 0, keyB = 0;
            int roiA = roi, roiB = -1;

            // probs >= 0 -> float bits monotone unsigned; 255-c resolves
            // ties to the lowest class index (matches jnp.argmax).
#define PROC_F(f) {                                                         \
            ull kk = ((ull)__float_as_uint(f) << 32) | (unsigned)(255 - c); \
            if (roi == roiA) { if (kk > keyA) keyA = kk; }                  \
            else             { roiB = roi; if (kk > keyB) keyB = kk; }      \
            if (++c == 81) { c = 0; ++roi; } }

#pragma unroll
            for (int u = 0; u < 6; u++) {
                bool act = (u < 5) | (q0 + u < q1);
                if (act) {
                    float4 v = __ldg(pq + q0 + u);
                    PROC_F(v.x) PROC_F(v.y) PROC_F(v.z) PROC_F(v.w)
                }
            }
#undef PROC_F
            atomicMax(slots + roiA, keyA);
            if (roiB >= 0) atomicMax(slots + roiB, keyB);
            __syncwarp();

            if (lane < 8) {
                ull  key = slots[lane];
                int   bi = 255 - (int)(key & 0xFFull);
                float sv = __uint_as_float((unsigned)(key >> 32));
                int   g  = task * 8 + lane;

                float4 d = __ldg((const float4*)deltas + ((size_t)g * CC + bi));
                float h  = myroi.z - myroi.x;
                float ww = myroi.w - myroi.y;
                float cy = myroi.x + 0.5f * h;
                float cx = myroi.y + 0.5f * ww;
                cy += d.x * 0.1f * h;
                cx += d.y * 0.1f * ww;
                h  *= expf(d.z * 0.2f);
                ww *= expf(d.w * 0.2f);
                float y1 = fminf(fmaxf(cy - 0.5f * h,  0.f), 1.f);
                float x1 = fminf(fmaxf(cx - 0.5f * ww, 0.f), 1.f);
                float y2 = fminf(fmaxf(cy + 0.5f * h,  0.f), 1.f);
                float x2 = fminf(fmaxf(cx + 0.5f * ww, 0.f), 1.f);

                bool valid = (bi > 0) && (sv >= MIN_CONF);
                int  b = g / NN;
                int  n = g - b * NN;
                int  o = b * NPAD + n;
                g_bx[o] = make_float4(y1, x1, y2, x2);
                g_cl[o] = bi;
                g_sc[o] = valid ? sv : -1.0f;
                if (valid) {
                    int cidx = b * 80 + (bi - 1);
                    int pos  = atomicAdd(&g_cnt[cidx], 1);
                    if (pos < MAXC) g_slot[cidx * MAXC + pos] = (unsigned short)n;
                }
            }
        }
    }

    grid_barrier(0);

    // ================= Phase 2: per-class NMS, full-chip spread =============
    // task = w*GRID + bid -> warps 0..8 active in every block (1280 tasks).
    // Cross-class IoU is exactly 0 (class offset 2 on clipped [0,1] boxes),
    // so per-class greedy == reference global greedy NMS.
    {
        float4* sbox = (float4*)(sraw + 2048);           // [9][64]
        float*  sar  = (float*) (sraw + 11264);          // [9][64]
        int gw = w * GRID + bid;
        if (gw < BB * 80) {
            int b  = gw / 80;
            int gb = b * NPAD;
            int cnt = min(g_cnt[gw], MAXC);

            ull k0 = 0, k1 = 0;
            if (lane < cnt) {
                int idx = g_slot[gw * MAXC + lane];
                k0 = ((ull)__float_as_uint(g_sc[gb + idx]) << 32) | (ull)(0xFFFFFFFFu - (unsigned)idx);
            }
            if (lane + 32 < cnt) {
                int idx = g_slot[gw * MAXC + lane + 32];
                k1 = ((ull)__float_as_uint(g_sc[gb + idx]) << 32) | (ull)(0xFFFFFFFFu - (unsigned)idx);
            }
            if (cnt <= 32) bsort32(k0, lane);
            else           bsort64(k0, k1, lane);

            bool v0 = (lane < cnt);
            bool v1 = (lane + 32 < cnt);
            int  i0 = (int)(0xFFFFFFFFu - (unsigned)k0);
            int  i1 = (int)(0xFFFFFFFFu - (unsigned)k1);
            float4 B0 = v0 ? g_bx[gb + i0] : make_float4(0.f, 0.f, 0.f, 0.f);
            float4 B1 = v1 ? g_bx[gb + i1] : make_float4(0.f, 0.f, 0.f, 0.f);
            float a0 = (B0.z - B0.x) * (B0.w - B0.y);
            float a1 = (B1.z - B1.x) * (B1.w - B1.y);
            sbox[w * MAXC + lane]      = B0;  sar[w * MAXC + lane]      = a0;
            sbox[w * MAXC + lane + 32] = B1;  sar[w * MAXC + lane + 32] = a1;
            __syncwarp();

            // forward masks: f bit j set iff j > e and IoU(e,j) > thresh
            ull f0 = 0, f1 = 0;
#pragma unroll 4
            for (int j = 0; j < cnt; j++) {
                float4 bj = sbox[w * MAXC + j];
                float  aj = sar [w * MAXC + j];
                if (v0 && j > lane) {
                    float ih = fmaxf(fminf(B0.z, bj.z) - fmaxf(B0.x, bj.x), 0.f);
                    float iw = fmaxf(fminf(B0.w, bj.w) - fmaxf(B0.y, bj.y), 0.f);
                    float inter = ih * iw;
                    if (inter > NMS_TH * fmaxf(a0 + aj - inter, 1e-8f)) f0 |= 1ull << j;
                }
                if (v1 && j > lane + 32) {
                    float ih = fmaxf(fminf(B1.z, bj.z) - fmaxf(B1.x, bj.x), 0.f);
                    float iw = fmaxf(fminf(B1.w, bj.w) - fmaxf(B1.y, bj.y), 0.f);
                    float inter = ih * iw;
                    if (inter > NMS_TH * fmaxf(a1 + aj - inter, 1e-8f)) f1 |= 1ull << j;
                }
            }

            // greedy: take best alive, keep it, kill whom it suppresses.
            // Iterations = number of kept boxes (warp-uniform).
            ull alive = (cnt >= 64) ? ~0ull : ((1ull << cnt) - 1ull);
            ull kept  = 0;
            while (alive) {
                int i = __ffsll((long long)alive) - 1;
                kept |= 1ull << i;
                ull fi = __shfl_sync(FULL, (i >= 32) ? f1 : f0, i & 31);
                alive &= ~fi;
                alive &= ~(1ull << i);
            }

            if (v0) g_keep[gb + i0] = (unsigned char)((kept >> lane) & 1ull);
            if (v1) g_keep[gb + i1] = (unsigned char)((kept >> (lane + 32)) & 1ull);
            if (lane == 0) g_cnt[gw] = 0;   // restore zero-invariant

            // release: writes visible, then signal this batch
            __threadfence();
            __syncwarp();
            if (lane == 0) atomicAdd(&g_ndone[b], 1);
        }
    }

    // Blocks 16+ are done: no second grid rendezvous.
    if (bid >= BB) return;

    __syncthreads();   // block-local: P2 warps done with sraw before reuse

    // ================= Phase 3: radix-select + rank-emit (blocks 0-15) ======
    {
        int*  hist = (int*)sraw;                 // [2048]
        ull*  cand = (ull*)(sraw + 8192);        // [256]
        int   b    = bid;
        int   gb   = b * NPAD;
        float* ob  = out + b * (MAXI * 6);

        // zero-init off the critical path (independent of P2 results)
        for (int i = t; i < 2048; i += 1024) hist[i] = 0;
        if (t == 0) { s_ncand = 0; s_bstar = 0; }
        for (int i = t; i < MAXI * 6; i += 1024) ob[i] = 0.0f;

        // wait until this batch's 80 NMS tasks are done (single poller)
        if (t == 0) {
            while (*(volatile int*)&g_ndone[b] < 80) { }
        }
        __syncthreads();
        __threadfence();   // acquire

        // histogram on float bits; kept => score in (0.7,1) -> bucket [819,2047]
        for (int i = t; i < NN; i += 1024) {
            if (g_keep[gb + i]) {
                unsigned bits = __float_as_uint(g_sc[gb + i]);
                int bk = (int)((bits - 0x3F000000u) >> 12);
                bk = min(2047, max(0, bk));
                atomicAdd(&hist[bk], 1);
            }
        }
        __syncthreads();

        // two-level suffix scan: thread t covers buckets {2t, 2t+1};
        // find b* = max bucket with suffix count >= 100 (unique transition)
        {
            int h0  = hist[2 * t];
            int h1  = hist[2 * t + 1];
            int loc = h0 + h1;
            int suf = loc;
            for (int d = 1; d < 32; d <<= 1) {
                int v = __shfl_down_sync(FULL, suf, d);
                if (lane + d < 32) suf += v;
            }
            if (lane == 0) wsum[w] = suf;
            __syncthreads();
            if (t == 0) {
                int acc = 0;
                for (int w2 = 31; w2 >= 0; w2--) { wsuf[w2] = acc; acc += wsum[w2]; }
            }
            __syncthreads();
            int run = wsuf[w] + (suf - loc);
            int S = run + h1;
            if (S >= MAXI && run < MAXI) s_bstar = 2 * t + 1;
            run = S;
            S = run + h0;
            if (S >= MAXI && run < MAXI) s_bstar = 2 * t;
        }
        __syncthreads();

        unsigned tbits = 0x3F000000u + ((unsigned)s_bstar << 12);
        for (int i = t; i < NN; i += 1024) {
            if (g_keep[gb + i]) {
                unsigned bits = __float_as_uint(g_sc[gb + i]);
                if (bits >= tbits) {
                    int p = atomicAdd(&s_ncand, 1);
                    if (p < 256)
                        cand[p] = ((ull)bits << 32) | (ull)(0xFFFFFFFFu - (unsigned)i);
                }
            }
        }
        __syncthreads();

        // rank-based emit: thread t handles candidate t; rank = number of
        // strictly greater keys (keys distinct). No sort, no barriers.
        int m = min(s_ncand, 256);
        if (t < m) {
            ull my = cand[t];
            int rank = 0;
            for (int j = 0; j < m; j++) rank += (cand[j] > my);
            if (rank < MAXI) {
                int idx = (int)(0xFFFFFFFFu - (unsigned)my);
                float sc = __uint_as_float((unsigned)(my >> 32));
                float4 bx = g_bx[gb + idx];
                float* row = ob + rank * 6;
                row[0] = bx.x; row[1] = bx.y; row[2] = bx.z; row[3] = bx.w;
                row[4] = (float)g_cl[gb + idx]; row[5] = sc;
            }
        }

        // restore zero-invariant for next graph replay
        if (t == 0) g_ndone[b] = 0;
    }
}

// ---------------------------------------------------------------------------
extern "C" void kernel_launch(void* const* d_in, const int* in_sizes, int n_in,
                              void* d_out, int out_size) {
    const float* rois   = nullptr;
    const float* probs  = nullptr;
    const float* deltas = nullptr;
    for (int i = 0; i < n_in; i++) {
        if      (in_sizes[i] == BB * NN * 4)      rois   = (const float*)d_in[i];
        else if (in_sizes[i] == BB * NN * CC)     probs  = (const float*)d_in[i];
        else if (in_sizes[i] == BB * NN * CC * 4) deltas = (const float*)d_in[i];
    }
    float* out = (float*)d_out;

    k_all<<<GRID, 1024>>>(rois, probs, deltas, out);
}

// round 14
// speedup vs baseline: 1.5161x; 1.0103x over previous
#include <cuda_runtime.h>
#include <math.h>

#define BB 16
#define NN 2000
#define CC 81
#define NPAD 2048
#define MAXC 64
#define MAXI 100
#define MIN_CONF 0.7f
#define NMS_TH 0.3f
#define FULL 0xffffffffu
#define RGRID 148

typedef unsigned long long ull;

// Scratch (static device globals — no runtime allocation).
// Zero-init invariants: g_cnt reset to 0 by NMS each run; g_ndone reset by
// select blocks; g_keep only ever written at candidate indices.
__device__ float4         g_bx[BB * NPAD];
__device__ float          g_sc[BB * NPAD];
__device__ int            g_cl[BB * NPAD];
__device__ unsigned char  g_keep[BB * NPAD];
__device__ int            g_cnt[BB * 80];
__device__ unsigned short g_slot[BB * 80 * MAXC];
__device__ int            g_ndone[BB];      // NMS tasks done per batch (80)

// ---------------------------------------------------------------------------
// K1: one warp per 4 ROIs (8000 warps — max parallelism), unrolled float4
// loads. Warp region = 324 floats = 81 float4s; lane owns 2-3 contiguous
// float4s (unroll-3, iter 2 predicated). Per-ROI packed argmax keys combine
// via 4 per-warp shared u64 atomicMax slots; 4 lanes run refine tails.
// ---------------------------------------------------------------------------
__global__ void __launch_bounds__(256) k_classify(const float* __restrict__ rois,
                                                  const float* __restrict__ probs,
                                                  const float* __restrict__ deltas) {
    __shared__ ull allslots[8][4];            // [warp][roi]
    int w    = threadIdx.x >> 5;
    int lane = threadIdx.x & 31;
    int task = blockIdx.x * 8 + w;
    if (task >= (BB * NN) / 4) return;

    ull* slots = allslots[w];
    if (lane < 4) slots[lane] = 0;
    __syncwarp();

    float4 myroi = make_float4(0.f, 0.f, 0.f, 0.f);
    if (lane < 4) myroi = __ldg((const float4*)rois + (task * 4 + lane));

    const float4* pq = (const float4*)(probs + (size_t)task * 324);
    int q0 = (81 * lane) >> 5;
    int q1 = (81 * (lane + 1)) >> 5;          // q1-q0 in {2,3}
    int p   = q0 * 4;
    int roi = p / 81;
    int c   = p - roi * 81;
    ull keyA = 0, keyB = 0;
    int roiA = roi, roiB = -1;

    // probs >= 0 -> float bits monotone unsigned; 255-c resolves ties to the
    // lowest class index under unsigned max (matches jnp.argmax).
#define PROC_F(f) {                                                         \
    ull kk = ((ull)__float_as_uint(f) << 32) | (unsigned)(255 - c);         \
    if (roi == roiA) { if (kk > keyA) keyA = kk; }                          \
    else             { roiB = roi; if (kk > keyB) keyB = kk; }              \
    if (++c == 81) { c = 0; ++roi; } }

#pragma unroll
    for (int u = 0; u < 3; u++) {
        bool act = (u < 2) | (q0 + u < q1);
        if (act) {
            float4 v = __ldg(pq + q0 + u);
            PROC_F(v.x) PROC_F(v.y) PROC_F(v.z) PROC_F(v.w)
        }
    }
#undef PROC_F
    atomicMax(slots + roiA, keyA);
    if (roiB >= 0) atomicMax(slots + roiB, keyB);
    __syncwarp();

    if (lane < 4) {
        ull  key = slots[lane];
        int   bi = 255 - (int)(key & 0xFFull);
        float sv = __uint_as_float((unsigned)(key >> 32));
        int   g  = task * 4 + lane;

        float4 d = __ldg((const float4*)deltas + ((size_t)g * CC + bi));
        float h  = myroi.z - myroi.x;
        float ww = myroi.w - myroi.y;
        float cy = myroi.x + 0.5f * h;
        float cx = myroi.y + 0.5f * ww;
        cy += d.x * 0.1f * h;
        cx += d.y * 0.1f * ww;
        h  *= expf(d.z * 0.2f);
        ww *= expf(d.w * 0.2f);
        float y1 = fminf(fmaxf(cy - 0.5f * h,  0.f), 1.f);
        float x1 = fminf(fmaxf(cx - 0.5f * ww, 0.f), 1.f);
        float y2 = fminf(fmaxf(cy + 0.5f * h,  0.f), 1.f);
        float x2 = fminf(fmaxf(cx + 0.5f * ww, 0.f), 1.f);

        bool valid = (bi > 0) && (sv >= MIN_CONF);
        int  b = g / NN;
        int  n = g - b * NN;
        int  o = b * NPAD + n;
        g_bx[o] = make_float4(y1, x1, y2, x2);
        g_cl[o] = bi;
        g_sc[o] = valid ? sv : -1.0f;
        if (valid) {
            int cidx = b * 80 + (bi - 1);
            int pos  = atomicAdd(&g_cnt[cidx], 1);
            if (pos < MAXC) g_slot[cidx * MAXC + pos] = (unsigned short)n;
        }
    }
}

// ---------------------------------------------------------------------------
// Warp-register bitonic sorts, descending. Pads (key 0) sink to the end.
// ---------------------------------------------------------------------------
__device__ __forceinline__ void bsort32(ull& k0, int lane) {
#pragma unroll
    for (int kk = 2; kk <= 32; kk <<= 1) {
#pragma unroll
        for (int d = kk >> 1; d > 0; d >>= 1) {
            ull o = __shfl_xor_sync(FULL, k0, d);
            bool lower = ((lane & d) == 0);
            bool asc   = ((lane & kk) == 0);
            k0 = (asc == lower) ? (k0 > o ? k0 : o) : (k0 > o ? o : k0);
        }
    }
}

__device__ __forceinline__ void bsort64(ull& k0, ull& k1, int lane) {
#pragma unroll
    for (int kk = 2; kk <= 64; kk <<= 1) {
#pragma unroll
        for (int d = kk >> 1; d > 0; d >>= 1) {
            if (d == 32) {
                ull mx = k0 > k1 ? k0 : k1;
                ull mn = k0 > k1 ? k1 : k0;
                k0 = mx; k1 = mn;
            } else {
                ull o0 = __shfl_xor_sync(FULL, k0, d);
                ull o1 = __shfl_xor_sync(FULL, k1, d);
                bool lower = ((lane & d) == 0);
                bool asc0  = ((lane & kk) == 0);
                bool asc1  = (((lane + 32) & kk) == 0);
                k0 = (asc0 == lower) ? (k0 > o0 ? k0 : o0) : (k0 > o0 ? o0 : k0);
                k1 = (asc1 == lower) ? (k1 > o1 ? k1 : o1) : (k1 > o1 ? o1 : k1);
            }
        }
    }
}

// ---------------------------------------------------------------------------
// K2 (persistent): NMS full-chip -> per-batch ready counters -> select on
// blocks 0-15; blocks 16+ exit after NMS. The kernel-launch boundary is the
// classify->NMS barrier.
// ---------------------------------------------------------------------------
__global__ void __launch_bounds__(1024, 1)
k_rest(float* __restrict__ out) {
    // smem: P2 sbox[9][64] float4 at [0,9216) + sar at [9216,11520)
    //       P3 hist[2048] int at [0,8192) + cand[256] ull at [8192,10240)
    __shared__ __align__(16) unsigned char sraw[11520];
    __shared__ int wsum[32];
    __shared__ int wsuf[32];
    __shared__ int s_ncand;
    __shared__ int s_bstar;

    int bid  = blockIdx.x;
    int t    = threadIdx.x;
    int w    = t >> 5;
    int lane = t & 31;

    // ================= Phase A: per-class NMS, full-chip spread =============
    // task = w*RGRID + bid -> warps 0..8 active in every block (1280 tasks).
    // Cross-class IoU is exactly 0 (class offset 2 on clipped [0,1] boxes),
    // so per-class greedy == reference global greedy NMS.
    {
        float4* sbox = (float4*)(sraw);                  // [9][64]
        float*  sar  = (float*) (sraw + 9216);           // [9][64]
        int gw = w * RGRID + bid;
        if (gw < BB * 80) {
            int b  = gw / 80;
            int gb = b * NPAD;
            int cnt = min(g_cnt[gw], MAXC);

            ull k0 = 0, k1 = 0;
            if (lane < cnt) {
                int idx = g_slot[gw * MAXC + lane];
                k0 = ((ull)__float_as_uint(g_sc[gb + idx]) << 32) | (ull)(0xFFFFFFFFu - (unsigned)idx);
            }
            if (lane + 32 < cnt) {
                int idx = g_slot[gw * MAXC + lane + 32];
                k1 = ((ull)__float_as_uint(g_sc[gb + idx]) << 32) | (ull)(0xFFFFFFFFu - (unsigned)idx);
            }
            if (cnt <= 32) bsort32(k0, lane);
            else           bsort64(k0, k1, lane);

            bool v0 = (lane < cnt);
            bool v1 = (lane + 32 < cnt);
            int  i0 = (int)(0xFFFFFFFFu - (unsigned)k0);
            int  i1 = (int)(0xFFFFFFFFu - (unsigned)k1);
            float4 B0 = v0 ? g_bx[gb + i0] : make_float4(0.f, 0.f, 0.f, 0.f);
            float4 B1 = v1 ? g_bx[gb + i1] : make_float4(0.f, 0.f, 0.f, 0.f);
            float a0 = (B0.z - B0.x) * (B0.w - B0.y);
            float a1 = (B1.z - B1.x) * (B1.w - B1.y);
            sbox[w * MAXC + lane]      = B0;  sar[w * MAXC + lane]      = a0;
            sbox[w * MAXC + lane + 32] = B1;  sar[w * MAXC + lane + 32] = a1;
            __syncwarp();

            // forward masks: f bit j set iff j > e and IoU(e,j) > thresh
            ull f0 = 0, f1 = 0;
#pragma unroll 4
            for (int j = 0; j < cnt; j++) {
                float4 bj = sbox[w * MAXC + j];
                float  aj = sar [w * MAXC + j];
                if (v0 && j > lane) {
                    float ih = fmaxf(fminf(B0.z, bj.z) - fmaxf(B0.x, bj.x), 0.f);
                    float iw = fmaxf(fminf(B0.w, bj.w) - fmaxf(B0.y, bj.y), 0.f);
                    float inter = ih * iw;
                    if (inter > NMS_TH * fmaxf(a0 + aj - inter, 1e-8f)) f0 |= 1ull << j;
                }
                if (v1 && j > lane + 32) {
                    float ih = fmaxf(fminf(B1.z, bj.z) - fmaxf(B1.x, bj.x), 0.f);
                    float iw = fmaxf(fminf(B1.w, bj.w) - fmaxf(B1.y, bj.y), 0.f);
                    float inter = ih * iw;
                    if (inter > NMS_TH * fmaxf(a1 + aj - inter, 1e-8f)) f1 |= 1ull << j;
                }
            }

            // greedy: take best alive, keep it, kill whom it suppresses.
            ull alive = (cnt >= 64) ? ~0ull : ((1ull << cnt) - 1ull);
            ull kept  = 0;
            while (alive) {
                int i = __ffsll((long long)alive) - 1;
                kept |= 1ull << i;
                ull fi = __shfl_sync(FULL, (i >= 32) ? f1 : f0, i & 31);
                alive &= ~fi;
                alive &= ~(1ull << i);
            }

            if (v0) g_keep[gb + i0] = (unsigned char)((kept >> lane) & 1ull);
            if (v1) g_keep[gb + i1] = (unsigned char)((kept >> (lane + 32)) & 1ull);
            if (lane == 0) g_cnt[gw] = 0;   // restore zero-invariant

            // release: writes visible, then signal this batch
            __threadfence();
            __syncwarp();
            if (lane == 0) atomicAdd(&g_ndone[b], 1);
        }
    }

    // Blocks 16+ are done.
    if (bid >= BB) return;

    __syncthreads();   // block-local: NMS warps done with sraw before reuse

    // ================= Phase B: radix-select + rank-emit ====================
    {
        int*  hist = (int*)sraw;                 // [2048]
        ull*  cand = (ull*)(sraw + 8192);        // [256]
        int   b    = bid;
        int   gb   = b * NPAD;
        float* ob  = out + b * (MAXI * 6);

        // zero-init off the critical path
        for (int i = t; i < 2048; i += 1024) hist[i] = 0;
        if (t == 0) { s_ncand = 0; s_bstar = 0; }
        for (int i = t; i < MAXI * 6; i += 1024) ob[i] = 0.0f;

        // wait until this batch's 80 NMS tasks are done (single poller)
        if (t == 0) {
            while (*(volatile int*)&g_ndone[b] < 80) { }
        }
        __syncthreads();
        __threadfence();   // acquire

        // histogram on float bits; kept => score in (0.7,1) -> bucket [819,2047]
        for (int i = t; i < NN; i += 1024) {
            if (g_keep[gb + i]) {
                unsigned bits = __float_as_uint(g_sc[gb + i]);
                int bk = (int)((bits - 0x3F000000u) >> 12);
                bk = min(2047, max(0, bk));
                atomicAdd(&hist[bk], 1);
            }
        }
        __syncthreads();

        // two-level suffix scan: thread t covers buckets {2t, 2t+1};
        // find b* = max bucket with suffix count >= 100 (unique transition)
        {
            int h0  = hist[2 * t];
            int h1  = hist[2 * t + 1];
            int loc = h0 + h1;
            int suf = loc;
            for (int d = 1; d < 32; d <<= 1) {
                int v = __shfl_down_sync(FULL, suf, d);
                if (lane + d < 32) suf += v;
            }
            if (lane == 0) wsum[w] = suf;
            __syncthreads();
            if (t == 0) {
                int acc = 0;
                for (int w2 = 31; w2 >= 0; w2--) { wsuf[w2] = acc; acc += wsum[w2]; }
            }
            __syncthreads();
            int run = wsuf[w] + (suf - loc);
            int S = run + h1;
            if (S >= MAXI && run < MAXI) s_bstar = 2 * t + 1;
            run = S;
            S = run + h0;
            if (S >= MAXI && run < MAXI) s_bstar = 2 * t;
        }
        __syncthreads();

        unsigned tbits = 0x3F000000u + ((unsigned)s_bstar << 12);
        for (int i = t; i < NN; i += 1024) {
            if (g_keep[gb + i]) {
                unsigned bits = __float_as_uint(g_sc[gb + i]);
                if (bits >= tbits) {
                    int p = atomicAdd(&s_ncand, 1);
                    if (p < 256)
                        cand[p] = ((ull)bits << 32) | (ull)(0xFFFFFFFFu - (unsigned)i);
                }
            }
        }
        __syncthreads();

        // rank-based emit: thread t handles candidate t; rank = number of
        // strictly greater keys (keys distinct). No sort, no barriers.
        int m = min(s_ncand, 256);
        if (t < m) {
            ull my = cand[t];
            int rank = 0;
            for (int j = 0; j < m; j++) rank += (cand[j] > my);
            if (rank < MAXI) {
                int idx = (int)(0xFFFFFFFFu - (unsigned)my);
                float sc = __uint_as_float((unsigned)(my >> 32));
                float4 bx = g_bx[gb + idx];
                float* row = ob + rank * 6;
                row[0] = bx.x; row[1] = bx.y; row[2] = bx.z; row[3] = bx.w;
                row[4] = (float)g_cl[gb + idx]; row[5] = sc;
            }
        }

        // restore zero-invariant for next graph replay
        if (t == 0) g_ndone[b] = 0;
    }
}

// ---------------------------------------------------------------------------
extern "C" void kernel_launch(void* const* d_in, const int* in_sizes, int n_in,
                              void* d_out, int out_size) {
    const float* rois   = nullptr;
    const float* probs  = nullptr;
    const float* deltas = nullptr;
    for (int i = 0; i < n_in; i++) {
        if      (in_sizes[i] == BB * NN * 4)      rois   = (const float*)d_in[i];
        else if (in_sizes[i] == BB * NN * CC)     probs  = (const float*)d_in[i];
        else if (in_sizes[i] == BB * NN * CC * 4) deltas = (const float*)d_in[i];
    }
    float* out = (float*)d_out;

    k_classify<<<BB * NN / 4 / 8, 256>>>(rois, probs, deltas); // 4 ROIs/warp
    k_rest    <<<RGRID, 1024>>>(out);                          // NMS + select
}

// round 15
// speedup vs baseline: 1.5260x; 1.0065x over previous
#include <cuda_runtime.h>
#include <math.h>

#define BB 16
#define NN 2000
#define CC 81
#define NPAD 2048
#define MAXC 64
#define MAXI 100
#define MIN_CONF 0.7f
#define NMS_TH 0.3f
#define FULL 0xffffffffu
#define RGRID 148

typedef unsigned long long ull;

// Scratch (static device globals — no runtime allocation).
// Zero-init invariants: g_cnt reset to 0 by NMS each run; g_ndone reset by
// k_classify of the NEXT run (kernel-boundary ordered — resetting inside
// k_rest would deadlock late redundant pollers); g_keep only ever written at
// candidate indices.
__device__ float4         g_bx[BB * NPAD];
__device__ float          g_sc[BB * NPAD];
__device__ int            g_cl[BB * NPAD];
__device__ unsigned char  g_keep[BB * NPAD];
__device__ int            g_cnt[BB * 80];
__device__ unsigned short g_slot[BB * 80 * MAXC];
__device__ int            g_ndone[BB];      // NMS tasks done per batch (80)

// ---------------------------------------------------------------------------
// K1: one warp per 4 ROIs (8000 warps), unrolled float4 loads. Lane owns 2-3
// contiguous float4s of the warp's 324-float probs region; per-ROI packed
// argmax keys combine via 4 per-warp shared u64 atomicMax slots; 4 lanes run
// refine tails concurrently. Also resets g_ndone for this run.
// ---------------------------------------------------------------------------
__global__ void __launch_bounds__(256) k_classify(const float* __restrict__ rois,
                                                  const float* __restrict__ probs,
                                                  const float* __restrict__ deltas) {
    __shared__ ull allslots[8][4];            // [warp][roi]
    int w    = threadIdx.x >> 5;
    int lane = threadIdx.x & 31;
    int task = blockIdx.x * 8 + w;

    if (blockIdx.x == 0 && threadIdx.x < BB) g_ndone[threadIdx.x] = 0;

    if (task >= (BB * NN) / 4) return;

    ull* slots = allslots[w];
    if (lane < 4) slots[lane] = 0;
    __syncwarp();

    float4 myroi = make_float4(0.f, 0.f, 0.f, 0.f);
    if (lane < 4) myroi = __ldg((const float4*)rois + (task * 4 + lane));

    const float4* pq = (const float4*)(probs + (size_t)task * 324);
    int q0 = (81 * lane) >> 5;
    int q1 = (81 * (lane + 1)) >> 5;          // q1-q0 in {2,3}
    int p   = q0 * 4;
    int roi = p / 81;
    int c   = p - roi * 81;
    ull keyA = 0, keyB = 0;
    int roiA = roi, roiB = -1;

    // probs >= 0 -> float bits monotone unsigned; 255-c resolves ties to the
    // lowest class index under unsigned max (matches jnp.argmax).
#define PROC_F(f) {                                                         \
    ull kk = ((ull)__float_as_uint(f) << 32) | (unsigned)(255 - c);         \
    if (roi == roiA) { if (kk > keyA) keyA = kk; }                          \
    else             { roiB = roi; if (kk > keyB) keyB = kk; }              \
    if (++c == 81) { c = 0; ++roi; } }

#pragma unroll
    for (int u = 0; u < 3; u++) {
        bool act = (u < 2) | (q0 + u < q1);
        if (act) {
            float4 v = __ldg(pq + q0 + u);
            PROC_F(v.x) PROC_F(v.y) PROC_F(v.z) PROC_F(v.w)
        }
    }
#undef PROC_F
    atomicMax(slots + roiA, keyA);
    if (roiB >= 0) atomicMax(slots + roiB, keyB);
    __syncwarp();

    if (lane < 4) {
        ull  key = slots[lane];
        int   bi = 255 - (int)(key & 0xFFull);
        float sv = __uint_as_float((unsigned)(key >> 32));
        int   g  = task * 4 + lane;

        float4 d = __ldg((const float4*)deltas + ((size_t)g * CC + bi));
        float h  = myroi.z - myroi.x;
        float ww = myroi.w - myroi.y;
        float cy = myroi.x + 0.5f * h;
        float cx = myroi.y + 0.5f * ww;
        cy += d.x * 0.1f * h;
        cx += d.y * 0.1f * ww;
        h  *= expf(d.z * 0.2f);
        ww *= expf(d.w * 0.2f);
        float y1 = fminf(fmaxf(cy - 0.5f * h,  0.f), 1.f);
        float x1 = fminf(fmaxf(cx - 0.5f * ww, 0.f), 1.f);
        float y2 = fminf(fmaxf(cy + 0.5f * h,  0.f), 1.f);
        float x2 = fminf(fmaxf(cx + 0.5f * ww, 0.f), 1.f);

        bool valid = (bi > 0) && (sv >= MIN_CONF);
        int  b = g / NN;
        int  n = g - b * NN;
        int  o = b * NPAD + n;
        g_bx[o] = make_float4(y1, x1, y2, x2);
        g_cl[o] = bi;
        g_sc[o] = valid ? sv : -1.0f;
        if (valid) {
            int cidx = b * 80 + (bi - 1);
            int pos  = atomicAdd(&g_cnt[cidx], 1);
            if (pos < MAXC) g_slot[cidx * MAXC + pos] = (unsigned short)n;
        }
    }
}

// ---------------------------------------------------------------------------
// Warp-register bitonic sorts, descending. Pads (key 0) sink to the end.
// ---------------------------------------------------------------------------
__device__ __forceinline__ void bsort32(ull& k0, int lane) {
#pragma unroll
    for (int kk = 2; kk <= 32; kk <<= 1) {
#pragma unroll
        for (int d = kk >> 1; d > 0; d >>= 1) {
            ull o = __shfl_xor_sync(FULL, k0, d);
            bool lower = ((lane & d) == 0);
            bool asc   = ((lane & kk) == 0);
            k0 = (asc == lower) ? (k0 > o ? k0 : o) : (k0 > o ? o : k0);
        }
    }
}

__device__ __forceinline__ void bsort64(ull& k0, ull& k1, int lane) {
#pragma unroll
    for (int kk = 2; kk <= 64; kk <<= 1) {
#pragma unroll
        for (int d = kk >> 1; d > 0; d >>= 1) {
            if (d == 32) {
                ull mx = k0 > k1 ? k0 : k1;
                ull mn = k0 > k1 ? k1 : k0;
                k0 = mx; k1 = mn;
            } else {
                ull o0 = __shfl_xor_sync(FULL, k0, d);
                ull o1 = __shfl_xor_sync(FULL, k1, d);
                bool lower = ((lane & d) == 0);
                bool asc0  = ((lane & kk) == 0);
                bool asc1  = (((lane + 32) & kk) == 0);
                k0 = (asc0 == lower) ? (k0 > o0 ? k0 : o0) : (k0 > o0 ? o0 : k0);
                k1 = (asc1 == lower) ? (k1 > o1 ? k1 : o1) : (k1 > o1 ? o1 : k1);
            }
        }
    }
}

// ---------------------------------------------------------------------------
// K2 (persistent, 148 blocks): NMS full-chip, then ALL blocks run select
// REDUNDANTLY (block bid -> batch bid%16, 9-10 blocks per batch computing
// identical results) so the chip never drops to 16 resident CTAs (low-grid
// issue-throttle avoidance). Output rows are staged in shared and every
// block writes the identical 600-float image -> no write race.
// ---------------------------------------------------------------------------
__global__ void __launch_bounds__(1024, 1)
k_rest(float* __restrict__ out) {
    // smem: NMS sbox[9][64] float4 [0,9216) + sar [9216,11520)
    //       select hist[2048] int [0,8192) + cand[256] ull [8192,10240)
    //              + srow[600] float [10240,12640)
    __shared__ __align__(16) unsigned char sraw[12640];
    __shared__ int s_ncand;
    __shared__ int s_bstar;

    int bid  = blockIdx.x;
    int t    = threadIdx.x;
    int w    = t >> 5;
    int lane = t & 31;

    // ================= Phase A: per-class NMS, full-chip spread =============
    // task = w*RGRID + bid -> warps 0..8 active in every block (1280 tasks).
    // Cross-class IoU is exactly 0 (class offset 2 on clipped [0,1] boxes),
    // so per-class greedy == reference global greedy NMS.
    {
        float4* sbox = (float4*)(sraw);                  // [9][64]
        float*  sar  = (float*) (sraw + 9216);           // [9][64]
        int gw = w * RGRID + bid;
        if (gw < BB * 80) {
            int b  = gw / 80;
            int gb = b * NPAD;
            int cnt = min(g_cnt[gw], MAXC);

            ull k0 = 0, k1 = 0;
            if (lane < cnt) {
                int idx = g_slot[gw * MAXC + lane];
                k0 = ((ull)__float_as_uint(g_sc[gb + idx]) << 32) | (ull)(0xFFFFFFFFu - (unsigned)idx);
            }
            if (lane + 32 < cnt) {
                int idx = g_slot[gw * MAXC + lane + 32];
                k1 = ((ull)__float_as_uint(g_sc[gb + idx]) << 32) | (ull)(0xFFFFFFFFu - (unsigned)idx);
            }
            if (cnt <= 32) bsort32(k0, lane);
            else           bsort64(k0, k1, lane);

            bool v0 = (lane < cnt);
            bool v1 = (lane + 32 < cnt);
            int  i0 = (int)(0xFFFFFFFFu - (unsigned)k0);
            int  i1 = (int)(0xFFFFFFFFu - (unsigned)k1);
            float4 B0 = v0 ? g_bx[gb + i0] : make_float4(0.f, 0.f, 0.f, 0.f);
            float4 B1 = v1 ? g_bx[gb + i1] : make_float4(0.f, 0.f, 0.f, 0.f);
            float a0 = (B0.z - B0.x) * (B0.w - B0.y);
            float a1 = (B1.z - B1.x) * (B1.w - B1.y);
            sbox[w * MAXC + lane]      = B0;  sar[w * MAXC + lane]      = a0;
            sbox[w * MAXC + lane + 32] = B1;  sar[w * MAXC + lane + 32] = a1;
            __syncwarp();

            // forward masks: f bit j set iff j > e and IoU(e,j) > thresh
            ull f0 = 0, f1 = 0;
#pragma unroll 4
            for (int j = 0; j < cnt; j++) {
                float4 bj = sbox[w * MAXC + j];
                float  aj = sar [w * MAXC + j];
                if (v0 && j > lane) {
                    float ih = fmaxf(fminf(B0.z, bj.z) - fmaxf(B0.x, bj.x), 0.f);
                    float iw = fmaxf(fminf(B0.w, bj.w) - fmaxf(B0.y, bj.y), 0.f);
                    float inter = ih * iw;
                    if (inter > NMS_TH * fmaxf(a0 + aj - inter, 1e-8f)) f0 |= 1ull << j;
                }
                if (v1 && j > lane + 32) {
                    float ih = fmaxf(fminf(B1.z, bj.z) - fmaxf(B1.x, bj.x), 0.f);
                    float iw = fmaxf(fminf(B1.w, bj.w) - fmaxf(B1.y, bj.y), 0.f);
                    float inter = ih * iw;
                    if (inter > NMS_TH * fmaxf(a1 + aj - inter, 1e-8f)) f1 |= 1ull << j;
                }
            }

            // greedy: take best alive, keep it, kill whom it suppresses.
            ull alive = (cnt >= 64) ? ~0ull : ((1ull << cnt) - 1ull);
            ull kept  = 0;
            while (alive) {
                int i = __ffsll((long long)alive) - 1;
                kept |= 1ull << i;
                ull fi = __shfl_sync(FULL, (i >= 32) ? f1 : f0, i & 31);
                alive &= ~fi;
                alive &= ~(1ull << i);
            }

            if (v0) g_keep[gb + i0] = (unsigned char)((kept >> lane) & 1ull);
            if (v1) g_keep[gb + i1] = (unsigned char)((kept >> (lane + 32)) & 1ull);
            if (lane == 0) g_cnt[gw] = 0;   // restore zero-invariant

            // release: writes visible, then signal this batch
            __threadfence();
            __syncwarp();
            if (lane == 0) atomicAdd(&g_ndone[gw / 80], 1);
        }
    }

    __syncthreads();   // NMS warps done with sraw before reuse

    // ================= Phase B: redundant select (all 148 blocks) ===========
    {
        int*   hist = (int*)sraw;                // [2048]
        ull*   cand = (ull*)(sraw + 8192);       // [256]
        float* srow = (float*)(sraw + 10240);    // [600]
        int    b    = bid & 15;                  // bid % 16
        int    gb   = b * NPAD;
        float* ob   = out + b * (MAXI * 6);

        // zero-init off the critical path (independent of NMS results)
        for (int i = t; i < 2048; i += 1024) hist[i] = 0;
        for (int i = t; i < MAXI * 6; i += 1024) srow[i] = 0.0f;
        if (t == 0) { s_ncand = 0; s_bstar = 0; }

        // wait until this batch's 80 NMS tasks are done (single poller).
        // g_ndone is NOT reset here (next k_classify resets it) so late
        // redundant pollers can never miss the signal.
        if (t == 0) {
            while (*(volatile int*)&g_ndone[b] < 80) { }
        }
        __syncthreads();
        __threadfence();   // acquire

        // histogram on float bits; kept => score in (0.7,1) -> bucket [819,2047]
        for (int i = t; i < NN; i += 1024) {
            if (g_keep[gb + i]) {
                unsigned bits = __float_as_uint(g_sc[gb + i]);
                int bk = (int)((bits - 0x3F000000u) >> 12);
                bk = min(2047, max(0, bk));
                atomicAdd(&hist[bk], 1);
            }
        }
        __syncthreads();

        // two-level suffix scan: thread t covers buckets {2t, 2t+1};
        // find b* = max bucket with suffix count >= 100 (unique transition)
        {
            __shared__ int wsum[32];
            __shared__ int wsuf[32];
            int h0  = hist[2 * t];
            int h1  = hist[2 * t + 1];
            int loc = h0 + h1;
            int suf = loc;
            for (int d = 1; d < 32; d <<= 1) {
                int v = __shfl_down_sync(FULL, suf, d);
                if (lane + d < 32) suf += v;
            }
            if (lane == 0) wsum[w] = suf;
            __syncthreads();
            if (t == 0) {
                int acc = 0;
                for (int w2 = 31; w2 >= 0; w2--) { wsuf[w2] = acc; acc += wsum[w2]; }
            }
            __syncthreads();
            int run = wsuf[w] + (suf - loc);
            int S = run + h1;
            if (S >= MAXI && run < MAXI) s_bstar = 2 * t + 1;
            run = S;
            S = run + h0;
            if (S >= MAXI && run < MAXI) s_bstar = 2 * t;
        }
        __syncthreads();

        unsigned tbits = 0x3F000000u + ((unsigned)s_bstar << 12);
        for (int i = t; i < NN; i += 1024) {
            if (g_keep[gb + i]) {
                unsigned bits = __float_as_uint(g_sc[gb + i]);
                if (bits >= tbits) {
                    int p = atomicAdd(&s_ncand, 1);
                    if (p < 256)
                        cand[p] = ((ull)bits << 32) | (ull)(0xFFFFFFFFu - (unsigned)i);
                }
            }
        }
        __syncthreads();

        // rank-based emit into shared staging: thread t handles candidate t;
        // rank = number of strictly greater keys (keys distinct, order-free).
        int m = min(s_ncand, 256);
        if (t < m) {
            ull my = cand[t];
            int rank = 0;
            for (int j = 0; j < m; j++) rank += (cand[j] > my);
            if (rank < MAXI) {
                int idx = (int)(0xFFFFFFFFu - (unsigned)my);
                float sc = __uint_as_float((unsigned)(my >> 32));
                float4 bx = g_bx[gb + idx];
                float* row = srow + rank * 6;
                row[0] = bx.x; row[1] = bx.y; row[2] = bx.z; row[3] = bx.w;
                row[4] = (float)g_cl[gb + idx]; row[5] = sc;
            }
        }
        __syncthreads();

        // every redundant block writes the IDENTICAL 600-float image
        for (int i = t; i < MAXI * 6; i += 1024) ob[i] = srow[i];
    }
}

// ---------------------------------------------------------------------------
extern "C" void kernel_launch(void* const* d_in, const int* in_sizes, int n_in,
                              void* d_out, int out_size) {
    const float* rois   = nullptr;
    const float* probs  = nullptr;
    const float* deltas = nullptr;
    for (int i = 0; i < n_in; i++) {
        if      (in_sizes[i] == BB * NN * 4)      rois   = (const float*)d_in[i];
        else if (in_sizes[i] == BB * NN * CC)     probs  = (const float*)d_in[i];
        else if (in_sizes[i] == BB * NN * CC * 4) deltas = (const float*)d_in[i];
    }
    float* out = (float*)d_out;

    k_classify<<<BB * NN / 4 / 8, 256>>>(rois, probs, deltas); // 4 ROIs/warp
    k_rest    <<<RGRID, 1024>>>(out);                          // NMS + redundant select
}